// round 2
// baseline (speedup 1.0000x reference)
#include <cuda_runtime.h>
#include <math.h>

typedef unsigned long long u64;
typedef unsigned int u32;

// ---------------- packed f32x2 helpers ----------------
__device__ __forceinline__ u64 dup2(float w) {
    u64 r; asm("mov.b64 %0, {%1, %1};" : "=l"(r) : "f"(w)); return r;
}
__device__ __forceinline__ void upk2(u64 v, float& a, float& b) {
    asm("mov.b64 {%0, %1}, %2;" : "=f"(a), "=f"(b) : "l"(v));
}
__device__ __forceinline__ u64 ffma2(u64 a, u64 b, u64 c) {
    u64 d; asm("fma.rn.f32x2 %0, %1, %2, %3;" : "=l"(d) : "l"(a), "l"(b), "l"(c)); return d;
}
__device__ __forceinline__ float gelu_exact(float x) {
    return 0.5f * x * (1.0f + erff(x * 0.70710678118654752f));
}

// ---------------- cp.async helpers ----------------
__device__ __forceinline__ void cp16(u32 dst, const void* src) {
    asm volatile("cp.async.cg.shared.global [%0], [%1], 16;\n" :: "r"(dst), "l"(src));
}
#define CP_COMMIT() asm volatile("cp.async.commit_group;\n" ::: "memory")
template <int N>
__device__ __forceinline__ void cp_wait() {
    asm volatile("cp.async.wait_group %0;\n" :: "n"(N) : "memory");
}

// ---------------- constants ----------------
#define BATCH 8
#define SEQ   4096
#define NCH   128
#define DIM   1024
#define NTOK  128             // tokens per block
#define SEG   4194304         // B*L*H*NB

// smem layout (float offsets)
#define XB0   0
#define XB1   8448            // 64*132
#define WB0   16896
#define WB1   25088           // +64*128
#define HSOFF 33280
#define SMEMF 50176           // total floats (200704 bytes)

// gmem scratch (static device globals -- allowed)
__device__ float  g_xT[32768 * 1024];          // transposed content_emb, 134 MB
__device__ float2 g_au[BATCH * SEQ * NCH];     // (alpha, u)
__device__ float2 g_agg[BATCH * 32 * NCH];     // per-chunk (A, U)
__device__ float  g_carry[BATCH * 32 * NCH];   // exclusive carry-in per chunk

// ---------------------------------------------------------------
// Transpose: ce [32768 tokens][1024] -> g_xT [tile(256)][k(1024)][t(128)]
// ---------------------------------------------------------------
__global__ void k_transpose(const float* __restrict__ ce) {
    __shared__ float sm[32][33];
    const int kt = blockIdx.x;   // k tile (32 k)
    const int tt = blockIdx.y;   // token tile (32 tokens)
    const int tx = threadIdx.x, ty = threadIdx.y;
#pragma unroll
    for (int r = 0; r < 4; ++r)
        sm[ty + 8 * r][tx] = ce[(tt * 32 + ty + 8 * r) * 1024 + kt * 32 + tx];
    __syncthreads();
    const int tile = tt >> 2;
    const int tl = (tt & 3) * 32 + tx;
#pragma unroll
    for (int r = 0; r < 4; ++r) {
        const int k = kt * 32 + ty + 8 * r;
        g_xT[tile * 131072 + k * 128 + tl] = sm[tx][ty + 8 * r];
    }
}

// ---------------------------------------------------------------
// 64-k-step accumulate: channel-packed f32x2.
// Thread tile: 8 channels (4 pairs) x 8 tokens.
// Xs: [64][132] floats (token-major rows). Ws: [64][128] floats.
// ---------------------------------------------------------------
__device__ __forceinline__ void mma_chunk64(const float* __restrict__ Xs,
                                            const float* __restrict__ Ws,
                                            int t0, int c0, u64 acc[4][8]) {
#pragma unroll 4
    for (int k = 0; k < 64; ++k) {
        const float4 xa = *(const float4*)(Xs + k * 132 + t0);
        const float4 xb = *(const float4*)(Xs + k * 132 + t0 + 4);
        const ulonglong2 wA = *(const ulonglong2*)(Ws + k * 128 + c0);
        const ulonglong2 wB = *(const ulonglong2*)(Ws + k * 128 + c0 + 4);
        u64 xd0 = dup2(xa.x), xd1 = dup2(xa.y), xd2 = dup2(xa.z), xd3 = dup2(xa.w);
        u64 xd4 = dup2(xb.x), xd5 = dup2(xb.y), xd6 = dup2(xb.z), xd7 = dup2(xb.w);
        u64 w0 = wA.x, w1 = wA.y, w2 = wB.x, w3 = wB.y;
        acc[0][0] = ffma2(xd0, w0, acc[0][0]); acc[0][1] = ffma2(xd1, w0, acc[0][1]);
        acc[0][2] = ffma2(xd2, w0, acc[0][2]); acc[0][3] = ffma2(xd3, w0, acc[0][3]);
        acc[0][4] = ffma2(xd4, w0, acc[0][4]); acc[0][5] = ffma2(xd5, w0, acc[0][5]);
        acc[0][6] = ffma2(xd6, w0, acc[0][6]); acc[0][7] = ffma2(xd7, w0, acc[0][7]);
        acc[1][0] = ffma2(xd0, w1, acc[1][0]); acc[1][1] = ffma2(xd1, w1, acc[1][1]);
        acc[1][2] = ffma2(xd2, w1, acc[1][2]); acc[1][3] = ffma2(xd3, w1, acc[1][3]);
        acc[1][4] = ffma2(xd4, w1, acc[1][4]); acc[1][5] = ffma2(xd5, w1, acc[1][5]);
        acc[1][6] = ffma2(xd6, w1, acc[1][6]); acc[1][7] = ffma2(xd7, w1, acc[1][7]);
        acc[2][0] = ffma2(xd0, w2, acc[2][0]); acc[2][1] = ffma2(xd1, w2, acc[2][1]);
        acc[2][2] = ffma2(xd2, w2, acc[2][2]); acc[2][3] = ffma2(xd3, w2, acc[2][3]);
        acc[2][4] = ffma2(xd4, w2, acc[2][4]); acc[2][5] = ffma2(xd5, w2, acc[2][5]);
        acc[2][6] = ffma2(xd6, w2, acc[2][6]); acc[2][7] = ffma2(xd7, w2, acc[2][7]);
        acc[3][0] = ffma2(xd0, w3, acc[3][0]); acc[3][1] = ffma2(xd1, w3, acc[3][1]);
        acc[3][2] = ffma2(xd2, w3, acc[3][2]); acc[3][3] = ffma2(xd3, w3, acc[3][3]);
        acc[3][4] = ffma2(xd4, w3, acc[3][4]); acc[3][5] = ffma2(xd5, w3, acc[3][5]);
        acc[3][6] = ffma2(xd6, w3, acc[3][6]); acc[3][7] = ffma2(xd7, w3, acc[3][7]);
    }
}

// stage one 64-k chunk of X (from g_xT tile) and W into buffer bufsel
__device__ __forceinline__ void stage_chunk(u32 sm0, int bufsel,
                                            const float* __restrict__ gX,
                                            const float* __restrict__ gW,
                                            int kc, int tid) {
    const float* srcX = gX + kc * 64 * 128;
    const float* srcW = gW + kc * 64 * 128;
    const u32 dX = sm0 + (bufsel ? XB1 : XB0) * 4u;
    const u32 dW = sm0 + (bufsel ? WB1 : WB0) * 4u;
#pragma unroll
    for (int i = 0; i < 8; ++i) {
        const int idx = i * 256 + tid;
        const int k = idx >> 5, j = (idx & 31) * 4;
        cp16(dX + (u32)(k * 132 + j) * 4u, srcX + k * 128 + j);
        cp16(dW + (u32)(k * 128 + j) * 4u, srcW + k * 128 + j);
    }
}

// stage full 128x128 layer2 weights into WB0..WB1 (contiguous)
__device__ __forceinline__ void stage_w2(u32 sm0, const float* __restrict__ gW2, int tid) {
    const u32 dW = sm0 + WB0 * 4u;
#pragma unroll
    for (int i = 0; i < 16; ++i) {
        const int idx = i * 256 + tid;
        const int k = idx >> 5, j = (idx & 31) * 4;
        cp16(dW + (u32)(k * 128 + j) * 4u, gW2 + k * 128 + j);
    }
}

// full 2-layer MLP for this block's 128-token tile; result (layer2 + bias2) in accOut
__device__ __forceinline__ void mlp_pass(const float* __restrict__ gW1, const float* __restrict__ gB1,
                                         const float* __restrict__ gW2, const float* __restrict__ gB2,
                                         const float* __restrict__ gXtile,
                                         float* smf, u32 sm0, int tid, int t0, int c0,
                                         u64 accOut[4][8]) {
    u64 acc1[4][8];
    {
        const u64* b1p = (const u64*)(gB1 + c0);
        u64 b0 = b1p[0], b1 = b1p[1], b2 = b1p[2], b3 = b1p[3];
#pragma unroll
        for (int t = 0; t < 8; ++t) { acc1[0][t] = b0; acc1[1][t] = b1; acc1[2][t] = b2; acc1[3][t] = b3; }
    }
    stage_chunk(sm0, 0, gXtile, gW1, 0, tid);
    CP_COMMIT();
#pragma unroll 1
    for (int kc = 0; kc < 16; ++kc) {
        if (kc < 15) {
            stage_chunk(sm0, (kc + 1) & 1, gXtile, gW1, kc + 1, tid);
            CP_COMMIT();
            cp_wait<1>();
        } else {
            cp_wait<0>();
        }
        __syncthreads();
        const float* Xs = smf + ((kc & 1) ? XB1 : XB0);
        const float* Ws = smf + ((kc & 1) ? WB1 : WB0);
        mma_chunk64(Xs, Ws, t0, c0, acc1);
        __syncthreads();
    }
    // GELU -> hs [hidden ch][token]
    float* hsm = smf + HSOFF;
#pragma unroll
    for (int cp = 0; cp < 4; ++cp) {
        float vA[8], vB[8];
#pragma unroll
        for (int j = 0; j < 8; ++j) {
            float lo, hi; upk2(acc1[cp][j], lo, hi);
            vA[j] = gelu_exact(lo); vB[j] = gelu_exact(hi);
        }
        float* rA = hsm + (c0 + 2 * cp) * 132 + t0;
        float* rB = rA + 132;
        *(float4*)rA       = make_float4(vA[0], vA[1], vA[2], vA[3]);
        *(float4*)(rA + 4) = make_float4(vA[4], vA[5], vA[6], vA[7]);
        *(float4*)rB       = make_float4(vB[0], vB[1], vB[2], vB[3]);
        *(float4*)(rB + 4) = make_float4(vB[4], vB[5], vB[6], vB[7]);
    }
    __syncthreads();
    // layer2
    stage_w2(sm0, gW2, tid);
    CP_COMMIT();
    cp_wait<0>();
    __syncthreads();
    {
        const u64* b2p = (const u64*)(gB2 + c0);
        u64 b0 = b2p[0], b1 = b2p[1], b2 = b2p[2], b3 = b2p[3];
#pragma unroll
        for (int t = 0; t < 8; ++t) { accOut[0][t] = b0; accOut[1][t] = b1; accOut[2][t] = b2; accOut[3][t] = b3; }
    }
    mma_chunk64(hsm,            smf + WB0,            t0, c0, accOut);
    mma_chunk64(hsm + 64 * 132, smf + WB0 + 64 * 128, t0, c0, accOut);
    __syncthreads();   // hs free for reuse by next MLP
}

// ---------------------------------------------------------------
// Kernel 1: both MLPs + pointwise. 256 blocks x 256 threads.
// ---------------------------------------------------------------
__global__ void __launch_bounds__(256, 1)
k_fused(const float* __restrict__ theta,
        const float* __restrict__ logQ, const float* __restrict__ logRa,
        const float* __restrict__ rw1, const float* __restrict__ rb1,
        const float* __restrict__ rw2, const float* __restrict__ rb2,
        const float* __restrict__ mw1, const float* __restrict__ mb1,
        const float* __restrict__ mw2, const float* __restrict__ mb2,
        float* __restrict__ out) {
    extern __shared__ float smf[];
    const u32 sm0 = (u32)__cvta_generic_to_shared(smf);
    const int tid = threadIdx.x;
    const int tile = blockIdx.x;
    const int n0 = tile * NTOK;
    const int t0 = (tid & 15) * 8;
    const int c0 = (tid >> 4) * 8;
    const float* gXtile = g_xT + (size_t)tile * 131072;

    // ---- MLP R ----
    u64 accR[4][8];
    mlp_pass(rw1, rb1, rw2, rb2, gXtile, smf, sm0, tid, t0, c0, accR);
    // R = exp(clip(.,-5,5)) -> write out segment 3 (also re-read at pointwise)
#pragma unroll
    for (int j = 0; j < 8; ++j) {
        float r8[8];
#pragma unroll
        for (int cp = 0; cp < 4; ++cp) {
            float lo, hi; upk2(accR[cp][j], lo, hi);
            r8[2 * cp]     = expf(fminf(fmaxf(lo, -5.0f), 5.0f));
            r8[2 * cp + 1] = expf(fminf(fmaxf(hi, -5.0f), 5.0f));
        }
        float* p = out + 3 * SEG + (n0 + t0 + j) * NCH + c0;
        *(float4*)p       = make_float4(r8[0], r8[1], r8[2], r8[3]);
        *(float4*)(p + 4) = make_float4(r8[4], r8[5], r8[6], r8[7]);
    }

    // ---- MLP M ----
    u64 accM[4][8];
    mlp_pass(mw1, mb1, mw2, mb2, gXtile, smf, sm0, tid, t0, c0, accM);

    // ---- Pi per channel ----
    float Pi8[8];
#pragma unroll
    for (int i = 0; i < 8; ++i) {
        const int c = c0 + i;
        const float q = expf(logQ[c]);
        const float ra = expf(logRa[c]);
        Pi8[i] = 0.5f * (sqrtf(q * q + 4.0f * q * ra) - q);
    }

    // ---- pointwise + outputs ----
    const float PI_F = 3.14159265358979323f;
    const float TWO_PI = 6.28318530717958648f;
    const float INV_2PI = 0.15915494309189535f;
#pragma unroll
    for (int j = 0; j < 8; ++j) {
        const int n = n0 + t0 + j;
        const int base = n * NCH + c0;
        float m8[8];
#pragma unroll
        for (int cp = 0; cp < 4; ++cp) upk2(accM[cp][j], m8[2 * cp], m8[2 * cp + 1]);
        const float4 ra4 = *(const float4*)(out + 3 * SEG + base);
        const float4 rb4 = *(const float4*)(out + 3 * SEG + base + 4);
        const float r8[8] = {ra4.x, ra4.y, ra4.z, ra4.w, rb4.x, rb4.y, rb4.z, rb4.w};
        const float4 ta4 = *(const float4*)(theta + base);
        const float4 tb4 = *(const float4*)(theta + base + 4);
        const float th8[8] = {ta4.x, ta4.y, ta4.z, ta4.w, tb4.x, tb4.y, tb4.z, tb4.w};
        float k8[8], av8[8], uv8[8];
#pragma unroll
        for (int i = 0; i < 8; ++i) {
            const float z = PI_F * tanhf(m8[i]);
            const float diff = z - th8[i];
            const float nu = diff - TWO_PI * rintf(diff * INV_2PI);
            const float Kv = Pi8[i] / fmaxf(Pi8[i] + r8[i], 1e-8f);
            k8[i] = Kv;
            av8[i] = 1.0f - Kv;
            uv8[i] = Kv * nu;
        }
        float* pp = out + SEG + base;
        *(float4*)pp       = make_float4(Pi8[0], Pi8[1], Pi8[2], Pi8[3]);
        *(float4*)(pp + 4) = make_float4(Pi8[4], Pi8[5], Pi8[6], Pi8[7]);
        float* pk = out + 2 * SEG + base;
        *(float4*)pk       = make_float4(k8[0], k8[1], k8[2], k8[3]);
        *(float4*)(pk + 4) = make_float4(k8[4], k8[5], k8[6], k8[7]);
        float* pa = (float*)g_au + 2 * base;
        *(float4*)pa        = make_float4(av8[0], uv8[0], av8[1], uv8[1]);
        *(float4*)(pa + 4)  = make_float4(av8[2], uv8[2], av8[3], uv8[3]);
        *(float4*)(pa + 8)  = make_float4(av8[4], uv8[4], av8[5], uv8[5]);
        *(float4*)(pa + 12) = make_float4(av8[6], uv8[6], av8[7], uv8[7]);
    }
}

// ---------------------------------------------------------------
// Scan kernels: chunked affine scan over seq dim (chunk = 128 steps)
// ---------------------------------------------------------------
__global__ void k_scanA() {
    const int c = blockIdx.x, b = blockIdx.y, t = threadIdx.x;
    int base = (b * SEQ + c * 128) * NCH + t;
    float A = 1.0f, U = 0.0f;
#pragma unroll 4
    for (int s = 0; s < 128; ++s) {
        float2 au = g_au[base + s * NCH];
        A *= au.x;
        U = fmaf(au.x, U, au.y);
    }
    g_agg[(b * 32 + c) * NCH + t] = make_float2(A, U);
}

__global__ void k_scanB() {
    const int b = blockIdx.x, t = threadIdx.x;
    float U = 0.0f;
#pragma unroll
    for (int c = 0; c < 32; ++c) {
        float2 g = g_agg[(b * 32 + c) * NCH + t];
        g_carry[(b * 32 + c) * NCH + t] = U;
        U = fmaf(g.x, U, g.y);
    }
}

__global__ void k_scanC(const float* __restrict__ theta, float* __restrict__ out) {
    const int c = blockIdx.x, b = blockIdx.y, t = threadIdx.x;
    int base = (b * SEQ + c * 128) * NCH + t;
    float d = g_carry[(b * 32 + c) * NCH + t];
#pragma unroll 4
    for (int s = 0; s < 128; ++s) {
        const int idx = base + s * NCH;
        float2 au = g_au[idx];
        d = fmaf(au.x, d, au.y);
        out[idx] = theta[idx] + d;
    }
}

// ---------------------------------------------------------------
extern "C" void kernel_launch(void* const* d_in, const int* in_sizes, int n_in,
                              void* d_out, int out_size) {
    const float* theta = (const float*)d_in[0];
    const float* ce    = (const float*)d_in[1];
    const float* logQ  = (const float*)d_in[2];
    const float* logRa = (const float*)d_in[3];
    const float* rw1   = (const float*)d_in[4];
    const float* rb1   = (const float*)d_in[5];
    const float* rw2   = (const float*)d_in[6];
    const float* rb2   = (const float*)d_in[7];
    const float* mw1   = (const float*)d_in[8];
    const float* mb1   = (const float*)d_in[9];
    const float* mw2   = (const float*)d_in[10];
    const float* mb2   = (const float*)d_in[11];
    float* out = (float*)d_out;

    k_transpose<<<dim3(32, 1024), dim3(32, 8)>>>(ce);

    const int smem = SMEMF * (int)sizeof(float);  // 200704 bytes
    cudaFuncSetAttribute(k_fused, cudaFuncAttributeMaxDynamicSharedMemorySize, smem);
    k_fused<<<256, 256, smem>>>(theta, logQ, logRa,
                                rw1, rb1, rw2, rb2,
                                mw1, mb1, mw2, mb2, out);

    k_scanA<<<dim3(32, BATCH), 128>>>();
    k_scanB<<<BATCH, 128>>>();
    k_scanC<<<dim3(32, BATCH), 128>>>(theta, out);
}

// round 3
// speedup vs baseline: 1.0087x; 1.0087x over previous
#include <cuda_runtime.h>
#include <math.h>

typedef unsigned long long u64;
typedef unsigned int u32;

// ---------------- packed f32x2 helpers ----------------
__device__ __forceinline__ u64 dup2(float w) {
    u64 r; asm("mov.b64 %0, {%1, %1};" : "=l"(r) : "f"(w)); return r;
}
__device__ __forceinline__ void upk2(u64 v, float& a, float& b) {
    asm("mov.b64 {%0, %1}, %2;" : "=f"(a), "=f"(b) : "l"(v));
}
__device__ __forceinline__ u64 ffma2(u64 a, u64 b, u64 c) {
    u64 d; asm("fma.rn.f32x2 %0, %1, %2, %3;" : "=l"(d) : "l"(a), "l"(b), "l"(c)); return d;
}
__device__ __forceinline__ float gelu_exact(float x) {
    return 0.5f * x * (1.0f + erff(x * 0.70710678118654752f));
}

// ---------------- cp.async helpers ----------------
__device__ __forceinline__ void cp16(u32 dst, const void* src) {
    asm volatile("cp.async.cg.shared.global [%0], [%1], 16;\n" :: "r"(dst), "l"(src));
}
#define CP_COMMIT() asm volatile("cp.async.commit_group;\n" ::: "memory")
template <int N>
__device__ __forceinline__ void cp_wait() {
    asm volatile("cp.async.wait_group %0;\n" :: "n"(N) : "memory");
}

// ---------------- constants ----------------
#define BATCH 8
#define SEQ   4096
#define NCH   128
#define DIM   1024
#define NTOK  128             // tokens per block
#define SEG   4194304         // B*L*H*NB

// smem layout (float offsets)
#define XB0   0
#define XB1   8448            // 64*132
#define WB0   16896
#define WB1   25088           // +64*128
#define HSOFF 33280
#define SMEMF 50176           // total floats (200704 bytes)

// gmem scratch (static device globals -- allowed)
__device__ float  g_xT[32768 * 1024];          // transposed content_emb, 134 MB
__device__ float2 g_au[BATCH * SEQ * NCH];     // (alpha, u)
__device__ float2 g_agg[BATCH * 32 * NCH];     // per-chunk (A, U)
__device__ float  g_carry[BATCH * 32 * NCH];   // exclusive carry-in per chunk

// ---------------------------------------------------------------
// Transpose: ce [32768 tokens][1024] -> g_xT [tile(256)][k(1024)][t(128)]
// ---------------------------------------------------------------
__global__ void k_transpose(const float* __restrict__ ce) {
    __shared__ float sm[32][33];
    const int kt = blockIdx.x;   // k tile (32 k)
    const int tt = blockIdx.y;   // token tile (32 tokens)
    const int tx = threadIdx.x, ty = threadIdx.y;
#pragma unroll
    for (int r = 0; r < 4; ++r)
        sm[ty + 8 * r][tx] = ce[(tt * 32 + ty + 8 * r) * 1024 + kt * 32 + tx];
    __syncthreads();
    const int tile = tt >> 2;
    const int tl = (tt & 3) * 32 + tx;
#pragma unroll
    for (int r = 0; r < 4; ++r) {
        const int k = kt * 32 + ty + 8 * r;
        g_xT[tile * 131072 + k * 128 + tl] = sm[tx][ty + 8 * r];
    }
}

// ---------------------------------------------------------------
// 64-k-step accumulate: channel-packed f32x2.
// Thread tile: 8 channels (4 pairs) x 8 tokens.
// Xs: [64][132] floats (token-major rows). Ws: [64][128] floats.
// ---------------------------------------------------------------
__device__ __forceinline__ void mma_chunk64(const float* __restrict__ Xs,
                                            const float* __restrict__ Ws,
                                            int t0, int c0, u64 acc[4][8]) {
#pragma unroll 4
    for (int k = 0; k < 64; ++k) {
        const float4 xa = *(const float4*)(Xs + k * 132 + t0);
        const float4 xb = *(const float4*)(Xs + k * 132 + t0 + 4);
        const ulonglong2 wA = *(const ulonglong2*)(Ws + k * 128 + c0);
        const ulonglong2 wB = *(const ulonglong2*)(Ws + k * 128 + c0 + 4);
        u64 xd0 = dup2(xa.x), xd1 = dup2(xa.y), xd2 = dup2(xa.z), xd3 = dup2(xa.w);
        u64 xd4 = dup2(xb.x), xd5 = dup2(xb.y), xd6 = dup2(xb.z), xd7 = dup2(xb.w);
        u64 w0 = wA.x, w1 = wA.y, w2 = wB.x, w3 = wB.y;
        acc[0][0] = ffma2(xd0, w0, acc[0][0]); acc[0][1] = ffma2(xd1, w0, acc[0][1]);
        acc[0][2] = ffma2(xd2, w0, acc[0][2]); acc[0][3] = ffma2(xd3, w0, acc[0][3]);
        acc[0][4] = ffma2(xd4, w0, acc[0][4]); acc[0][5] = ffma2(xd5, w0, acc[0][5]);
        acc[0][6] = ffma2(xd6, w0, acc[0][6]); acc[0][7] = ffma2(xd7, w0, acc[0][7]);
        acc[1][0] = ffma2(xd0, w1, acc[1][0]); acc[1][1] = ffma2(xd1, w1, acc[1][1]);
        acc[1][2] = ffma2(xd2, w1, acc[1][2]); acc[1][3] = ffma2(xd3, w1, acc[1][3]);
        acc[1][4] = ffma2(xd4, w1, acc[1][4]); acc[1][5] = ffma2(xd5, w1, acc[1][5]);
        acc[1][6] = ffma2(xd6, w1, acc[1][6]); acc[1][7] = ffma2(xd7, w1, acc[1][7]);
        acc[2][0] = ffma2(xd0, w2, acc[2][0]); acc[2][1] = ffma2(xd1, w2, acc[2][1]);
        acc[2][2] = ffma2(xd2, w2, acc[2][2]); acc[2][3] = ffma2(xd3, w2, acc[2][3]);
        acc[2][4] = ffma2(xd4, w2, acc[2][4]); acc[2][5] = ffma2(xd5, w2, acc[2][5]);
        acc[2][6] = ffma2(xd6, w2, acc[2][6]); acc[2][7] = ffma2(xd7, w2, acc[2][7]);
        acc[3][0] = ffma2(xd0, w3, acc[3][0]); acc[3][1] = ffma2(xd1, w3, acc[3][1]);
        acc[3][2] = ffma2(xd2, w3, acc[3][2]); acc[3][3] = ffma2(xd3, w3, acc[3][3]);
        acc[3][4] = ffma2(xd4, w3, acc[3][4]); acc[3][5] = ffma2(xd5, w3, acc[3][5]);
        acc[3][6] = ffma2(xd6, w3, acc[3][6]); acc[3][7] = ffma2(xd7, w3, acc[3][7]);
    }
}

// stage one 64-k chunk of X (from g_xT tile) and W into buffer bufsel
__device__ __forceinline__ void stage_chunk(u32 sm0, int bufsel,
                                            const float* __restrict__ gX,
                                            const float* __restrict__ gW,
                                            int kc, int tid) {
    const float* srcX = gX + kc * 64 * 128;
    const float* srcW = gW + kc * 64 * 128;
    const u32 dX = sm0 + (bufsel ? XB1 : XB0) * 4u;
    const u32 dW = sm0 + (bufsel ? WB1 : WB0) * 4u;
#pragma unroll
    for (int i = 0; i < 8; ++i) {
        const int idx = i * 256 + tid;
        const int k = idx >> 5, j = (idx & 31) * 4;
        cp16(dX + (u32)(k * 132 + j) * 4u, srcX + k * 128 + j);
        cp16(dW + (u32)(k * 128 + j) * 4u, srcW + k * 128 + j);
    }
}

// stage full 128x128 layer2 weights into WB0..WB1 (contiguous)
__device__ __forceinline__ void stage_w2(u32 sm0, const float* __restrict__ gW2, int tid) {
    const u32 dW = sm0 + WB0 * 4u;
#pragma unroll
    for (int i = 0; i < 16; ++i) {
        const int idx = i * 256 + tid;
        const int k = idx >> 5, j = (idx & 31) * 4;
        cp16(dW + (u32)(k * 128 + j) * 4u, gW2 + k * 128 + j);
    }
}

// full 2-layer MLP for this block's 128-token tile; result (layer2 + bias2) in accOut
__device__ __forceinline__ void mlp_pass(const float* __restrict__ gW1, const float* __restrict__ gB1,
                                         const float* __restrict__ gW2, const float* __restrict__ gB2,
                                         const float* __restrict__ gXtile,
                                         float* smf, u32 sm0, int tid, int t0, int c0,
                                         u64 accOut[4][8]) {
    u64 acc1[4][8];
    {
        const u64* b1p = (const u64*)(gB1 + c0);
        u64 b0 = b1p[0], b1 = b1p[1], b2 = b1p[2], b3 = b1p[3];
#pragma unroll
        for (int t = 0; t < 8; ++t) { acc1[0][t] = b0; acc1[1][t] = b1; acc1[2][t] = b2; acc1[3][t] = b3; }
    }
    stage_chunk(sm0, 0, gXtile, gW1, 0, tid);
    CP_COMMIT();
#pragma unroll 1
    for (int kc = 0; kc < 16; ++kc) {
        if (kc < 15) {
            stage_chunk(sm0, (kc + 1) & 1, gXtile, gW1, kc + 1, tid);
            CP_COMMIT();
            cp_wait<1>();
        } else {
            cp_wait<0>();
        }
        __syncthreads();
        const float* Xs = smf + ((kc & 1) ? XB1 : XB0);
        const float* Ws = smf + ((kc & 1) ? WB1 : WB0);
        mma_chunk64(Xs, Ws, t0, c0, acc1);
        __syncthreads();
    }
    // GELU -> hs [hidden ch][token]
    float* hsm = smf + HSOFF;
#pragma unroll
    for (int cp = 0; cp < 4; ++cp) {
        float vA[8], vB[8];
#pragma unroll
        for (int j = 0; j < 8; ++j) {
            float lo, hi; upk2(acc1[cp][j], lo, hi);
            vA[j] = gelu_exact(lo); vB[j] = gelu_exact(hi);
        }
        float* rA = hsm + (c0 + 2 * cp) * 132 + t0;
        float* rB = rA + 132;
        *(float4*)rA       = make_float4(vA[0], vA[1], vA[2], vA[3]);
        *(float4*)(rA + 4) = make_float4(vA[4], vA[5], vA[6], vA[7]);
        *(float4*)rB       = make_float4(vB[0], vB[1], vB[2], vB[3]);
        *(float4*)(rB + 4) = make_float4(vB[4], vB[5], vB[6], vB[7]);
    }
    __syncthreads();
    // layer2
    stage_w2(sm0, gW2, tid);
    CP_COMMIT();
    cp_wait<0>();
    __syncthreads();
    {
        const u64* b2p = (const u64*)(gB2 + c0);
        u64 b0 = b2p[0], b1 = b2p[1], b2 = b2p[2], b3 = b2p[3];
#pragma unroll
        for (int t = 0; t < 8; ++t) { accOut[0][t] = b0; accOut[1][t] = b1; accOut[2][t] = b2; accOut[3][t] = b3; }
    }
    mma_chunk64(hsm,            smf + WB0,            t0, c0, accOut);
    mma_chunk64(hsm + 64 * 132, smf + WB0 + 64 * 128, t0, c0, accOut);
    __syncthreads();   // hs free for reuse by next MLP
}

// ---------------------------------------------------------------
// Kernel 1: both MLPs + pointwise. 256 blocks x 256 threads.
// ---------------------------------------------------------------
__global__ void __launch_bounds__(256, 1)
k_fused(const float* __restrict__ theta,
        const float* __restrict__ logQ, const float* __restrict__ logRa,
        const float* __restrict__ rw1, const float* __restrict__ rb1,
        const float* __restrict__ rw2, const float* __restrict__ rb2,
        const float* __restrict__ mw1, const float* __restrict__ mb1,
        const float* __restrict__ mw2, const float* __restrict__ mb2,
        float* __restrict__ out) {
    extern __shared__ float smf[];
    const u32 sm0 = (u32)__cvta_generic_to_shared(smf);
    const int tid = threadIdx.x;
    const int tile = blockIdx.x;
    const int n0 = tile * NTOK;
    const int t0 = (tid & 15) * 8;
    const int c0 = (tid >> 4) * 8;
    const float* gXtile = g_xT + (size_t)tile * 131072;

    // ---- MLP R ----
    u64 accR[4][8];
    mlp_pass(rw1, rb1, rw2, rb2, gXtile, smf, sm0, tid, t0, c0, accR);
    // R = exp(clip(.,-5,5)) -> write out segment 3 (also re-read at pointwise)
#pragma unroll
    for (int j = 0; j < 8; ++j) {
        float r8[8];
#pragma unroll
        for (int cp = 0; cp < 4; ++cp) {
            float lo, hi; upk2(accR[cp][j], lo, hi);
            r8[2 * cp]     = expf(fminf(fmaxf(lo, -5.0f), 5.0f));
            r8[2 * cp + 1] = expf(fminf(fmaxf(hi, -5.0f), 5.0f));
        }
        float* p = out + 3 * SEG + (n0 + t0 + j) * NCH + c0;
        *(float4*)p       = make_float4(r8[0], r8[1], r8[2], r8[3]);
        *(float4*)(p + 4) = make_float4(r8[4], r8[5], r8[6], r8[7]);
    }

    // ---- MLP M ----
    u64 accM[4][8];
    mlp_pass(mw1, mb1, mw2, mb2, gXtile, smf, sm0, tid, t0, c0, accM);

    // ---- Pi per channel ----
    float Pi8[8];
#pragma unroll
    for (int i = 0; i < 8; ++i) {
        const int c = c0 + i;
        const float q = expf(logQ[c]);
        const float ra = expf(logRa[c]);
        Pi8[i] = 0.5f * (sqrtf(q * q + 4.0f * q * ra) - q);
    }

    // ---- pointwise + outputs ----
    const float PI_F = 3.14159265358979323f;
    const float TWO_PI = 6.28318530717958648f;
    const float INV_2PI = 0.15915494309189535f;
#pragma unroll
    for (int j = 0; j < 8; ++j) {
        const int n = n0 + t0 + j;
        const int base = n * NCH + c0;
        float m8[8];
#pragma unroll
        for (int cp = 0; cp < 4; ++cp) upk2(accM[cp][j], m8[2 * cp], m8[2 * cp + 1]);
        const float4 ra4 = *(const float4*)(out + 3 * SEG + base);
        const float4 rb4 = *(const float4*)(out + 3 * SEG + base + 4);
        const float r8[8] = {ra4.x, ra4.y, ra4.z, ra4.w, rb4.x, rb4.y, rb4.z, rb4.w};
        const float4 ta4 = *(const float4*)(theta + base);
        const float4 tb4 = *(const float4*)(theta + base + 4);
        const float th8[8] = {ta4.x, ta4.y, ta4.z, ta4.w, tb4.x, tb4.y, tb4.z, tb4.w};
        float k8[8], av8[8], uv8[8];
#pragma unroll
        for (int i = 0; i < 8; ++i) {
            const float z = PI_F * tanhf(m8[i]);
            const float diff = z - th8[i];
            const float nu = diff - TWO_PI * rintf(diff * INV_2PI);
            const float Kv = Pi8[i] / fmaxf(Pi8[i] + r8[i], 1e-8f);
            k8[i] = Kv;
            av8[i] = 1.0f - Kv;
            uv8[i] = Kv * nu;
        }
        float* pp = out + SEG + base;
        *(float4*)pp       = make_float4(Pi8[0], Pi8[1], Pi8[2], Pi8[3]);
        *(float4*)(pp + 4) = make_float4(Pi8[4], Pi8[5], Pi8[6], Pi8[7]);
        float* pk = out + 2 * SEG + base;
        *(float4*)pk       = make_float4(k8[0], k8[1], k8[2], k8[3]);
        *(float4*)(pk + 4) = make_float4(k8[4], k8[5], k8[6], k8[7]);
        float* pa = (float*)g_au + 2 * base;
        *(float4*)pa        = make_float4(av8[0], uv8[0], av8[1], uv8[1]);
        *(float4*)(pa + 4)  = make_float4(av8[2], uv8[2], av8[3], uv8[3]);
        *(float4*)(pa + 8)  = make_float4(av8[4], uv8[4], av8[5], uv8[5]);
        *(float4*)(pa + 12) = make_float4(av8[6], uv8[6], av8[7], uv8[7]);
    }
}

// ---------------------------------------------------------------
// Scan kernels: chunked affine scan over seq dim (chunk = 128 steps)
// ---------------------------------------------------------------
__global__ void k_scanA() {
    const int c = blockIdx.x, b = blockIdx.y, t = threadIdx.x;
    int base = (b * SEQ + c * 128) * NCH + t;
    float A = 1.0f, U = 0.0f;
#pragma unroll 4
    for (int s = 0; s < 128; ++s) {
        float2 au = g_au[base + s * NCH];
        A *= au.x;
        U = fmaf(au.x, U, au.y);
    }
    g_agg[(b * 32 + c) * NCH + t] = make_float2(A, U);
}

__global__ void k_scanB() {
    const int b = blockIdx.x, t = threadIdx.x;
    float U = 0.0f;
#pragma unroll
    for (int c = 0; c < 32; ++c) {
        float2 g = g_agg[(b * 32 + c) * NCH + t];
        g_carry[(b * 32 + c) * NCH + t] = U;
        U = fmaf(g.x, U, g.y);
    }
}

__global__ void k_scanC(const float* __restrict__ theta, float* __restrict__ out) {
    const int c = blockIdx.x, b = blockIdx.y, t = threadIdx.x;
    int base = (b * SEQ + c * 128) * NCH + t;
    float d = g_carry[(b * 32 + c) * NCH + t];
#pragma unroll 4
    for (int s = 0; s < 128; ++s) {
        const int idx = base + s * NCH;
        float2 au = g_au[idx];
        d = fmaf(au.x, d, au.y);
        out[idx] = theta[idx] + d;
    }
}

// ---------------------------------------------------------------
extern "C" void kernel_launch(void* const* d_in, const int* in_sizes, int n_in,
                              void* d_out, int out_size) {
    const float* theta = (const float*)d_in[0];
    const float* ce    = (const float*)d_in[1];
    const float* logQ  = (const float*)d_in[2];
    const float* logRa = (const float*)d_in[3];
    const float* rw1   = (const float*)d_in[4];
    const float* rb1   = (const float*)d_in[5];
    const float* rw2   = (const float*)d_in[6];
    const float* rb2   = (const float*)d_in[7];
    const float* mw1   = (const float*)d_in[8];
    const float* mb1   = (const float*)d_in[9];
    const float* mw2   = (const float*)d_in[10];
    const float* mb2   = (const float*)d_in[11];
    float* out = (float*)d_out;

    k_transpose<<<dim3(32, 1024), dim3(32, 8)>>>(ce);

    const int smem = SMEMF * (int)sizeof(float);  // 200704 bytes
    cudaFuncSetAttribute(k_fused, cudaFuncAttributeMaxDynamicSharedMemorySize, smem);
    k_fused<<<256, 256, smem>>>(theta, logQ, logRa,
                                rw1, rb1, rw2, rb2,
                                mw1, mb1, mw2, mb2, out);

    k_scanA<<<dim3(32, BATCH), 128>>>();
    k_scanB<<<BATCH, 128>>>();
    k_scanC<<<dim3(32, BATCH), 128>>>(theta, out);
}

// round 4
// speedup vs baseline: 1.0097x; 1.0010x over previous
#include <cuda_runtime.h>
#include <math.h>

typedef unsigned long long u64;
typedef unsigned int u32;

// ---------------- packed f32x2 helpers ----------------
__device__ __forceinline__ u64 dup2(float w) {
    u64 r; asm("mov.b64 %0, {%1, %1};" : "=l"(r) : "f"(w)); return r;
}
__device__ __forceinline__ void upk2(u64 v, float& a, float& b) {
    asm("mov.b64 {%0, %1}, %2;" : "=f"(a), "=f"(b) : "l"(v));
}
__device__ __forceinline__ u64 ffma2(u64 a, u64 b, u64 c) {
    u64 d; asm("fma.rn.f32x2 %0, %1, %2, %3;" : "=l"(d) : "l"(a), "l"(b), "l"(c)); return d;
}
__device__ __forceinline__ float gelu_exact(float x) {
    return 0.5f * x * (1.0f + erff(x * 0.70710678118654752f));
}

// ---------------- cp.async helpers ----------------
__device__ __forceinline__ void cp16(u32 dst, const void* src) {
    asm volatile("cp.async.cg.shared.global [%0], [%1], 16;\n" :: "r"(dst), "l"(src));
}
#define CP_COMMIT() asm volatile("cp.async.commit_group;\n" ::: "memory")
template <int N>
__device__ __forceinline__ void cp_wait() {
    asm volatile("cp.async.wait_group %0;\n" :: "n"(N) : "memory");
}

// ---------------- constants ----------------
#define BATCH 8
#define SEQ   4096
#define NCH   128
#define DIM   1024
#define NTOK  128             // tokens per block
#define SEG   4194304         // B*L*H*NB

// smem layout (float offsets)
#define XB0   0
#define XB1   8448            // 64*132
#define WB0   16896
#define WB1   25088           // +64*128
#define HSOFF 33280
#define SMEMF 50176           // total floats (200704 bytes)

// gmem scratch (static device globals -- allowed)
__device__ float  g_xT[32768 * 1024];          // transposed content_emb, 134 MB
__device__ float2 g_au[BATCH * SEQ * NCH];     // (alpha, u)
__device__ float2 g_agg[BATCH * 32 * NCH];     // per-chunk (A, U)
__device__ float  g_carry[BATCH * 32 * NCH];   // exclusive carry-in per chunk

// ---------------------------------------------------------------
// Transpose: ce [32768 tokens][1024] -> g_xT [tile(256)][k(1024)][t(128)]
// ---------------------------------------------------------------
__global__ void k_transpose(const float* __restrict__ ce) {
    __shared__ float sm[32][33];
    const int kt = blockIdx.x;   // k tile (32 k)
    const int tt = blockIdx.y;   // token tile (32 tokens)
    const int tx = threadIdx.x, ty = threadIdx.y;
#pragma unroll
    for (int r = 0; r < 4; ++r)
        sm[ty + 8 * r][tx] = ce[(tt * 32 + ty + 8 * r) * 1024 + kt * 32 + tx];
    __syncthreads();
    const int tile = tt >> 2;
    const int tl = (tt & 3) * 32 + tx;
#pragma unroll
    for (int r = 0; r < 4; ++r) {
        const int k = kt * 32 + ty + 8 * r;
        g_xT[tile * 131072 + k * 128 + tl] = sm[tx][ty + 8 * r];
    }
}

// ---------------------------------------------------------------
// 64-k-step accumulate: channel-packed f32x2.
// Thread tile: 8 channels (4 pairs) x 8 tokens.
// Xs: [64][132] floats (token-major rows). Ws: [64][128] floats.
// ---------------------------------------------------------------
__device__ __forceinline__ void mma_chunk64(const float* __restrict__ Xs,
                                            const float* __restrict__ Ws,
                                            int t0, int c0, u64 acc[4][8]) {
#pragma unroll 4
    for (int k = 0; k < 64; ++k) {
        const float4 xa = *(const float4*)(Xs + k * 132 + t0);
        const float4 xb = *(const float4*)(Xs + k * 132 + t0 + 4);
        const ulonglong2 wA = *(const ulonglong2*)(Ws + k * 128 + c0);
        const ulonglong2 wB = *(const ulonglong2*)(Ws + k * 128 + c0 + 4);
        u64 xd0 = dup2(xa.x), xd1 = dup2(xa.y), xd2 = dup2(xa.z), xd3 = dup2(xa.w);
        u64 xd4 = dup2(xb.x), xd5 = dup2(xb.y), xd6 = dup2(xb.z), xd7 = dup2(xb.w);
        u64 w0 = wA.x, w1 = wA.y, w2 = wB.x, w3 = wB.y;
        acc[0][0] = ffma2(xd0, w0, acc[0][0]); acc[0][1] = ffma2(xd1, w0, acc[0][1]);
        acc[0][2] = ffma2(xd2, w0, acc[0][2]); acc[0][3] = ffma2(xd3, w0, acc[0][3]);
        acc[0][4] = ffma2(xd4, w0, acc[0][4]); acc[0][5] = ffma2(xd5, w0, acc[0][5]);
        acc[0][6] = ffma2(xd6, w0, acc[0][6]); acc[0][7] = ffma2(xd7, w0, acc[0][7]);
        acc[1][0] = ffma2(xd0, w1, acc[1][0]); acc[1][1] = ffma2(xd1, w1, acc[1][1]);
        acc[1][2] = ffma2(xd2, w1, acc[1][2]); acc[1][3] = ffma2(xd3, w1, acc[1][3]);
        acc[1][4] = ffma2(xd4, w1, acc[1][4]); acc[1][5] = ffma2(xd5, w1, acc[1][5]);
        acc[1][6] = ffma2(xd6, w1, acc[1][6]); acc[1][7] = ffma2(xd7, w1, acc[1][7]);
        acc[2][0] = ffma2(xd0, w2, acc[2][0]); acc[2][1] = ffma2(xd1, w2, acc[2][1]);
        acc[2][2] = ffma2(xd2, w2, acc[2][2]); acc[2][3] = ffma2(xd3, w2, acc[2][3]);
        acc[2][4] = ffma2(xd4, w2, acc[2][4]); acc[2][5] = ffma2(xd5, w2, acc[2][5]);
        acc[2][6] = ffma2(xd6, w2, acc[2][6]); acc[2][7] = ffma2(xd7, w2, acc[2][7]);
        acc[3][0] = ffma2(xd0, w3, acc[3][0]); acc[3][1] = ffma2(xd1, w3, acc[3][1]);
        acc[3][2] = ffma2(xd2, w3, acc[3][2]); acc[3][3] = ffma2(xd3, w3, acc[3][3]);
        acc[3][4] = ffma2(xd4, w3, acc[3][4]); acc[3][5] = ffma2(xd5, w3, acc[3][5]);
        acc[3][6] = ffma2(xd6, w3, acc[3][6]); acc[3][7] = ffma2(xd7, w3, acc[3][7]);
    }
}

// stage one 64-k chunk of X (from g_xT tile) and W into buffer bufsel
__device__ __forceinline__ void stage_chunk(u32 sm0, int bufsel,
                                            const float* __restrict__ gX,
                                            const float* __restrict__ gW,
                                            int kc, int tid) {
    const float* srcX = gX + kc * 64 * 128;
    const float* srcW = gW + kc * 64 * 128;
    const u32 dX = sm0 + (bufsel ? XB1 : XB0) * 4u;
    const u32 dW = sm0 + (bufsel ? WB1 : WB0) * 4u;
#pragma unroll
    for (int i = 0; i < 8; ++i) {
        const int idx = i * 256 + tid;
        const int k = idx >> 5, j = (idx & 31) * 4;
        cp16(dX + (u32)(k * 132 + j) * 4u, srcX + k * 128 + j);
        cp16(dW + (u32)(k * 128 + j) * 4u, srcW + k * 128 + j);
    }
}

// stage full 128x128 layer2 weights into WB0..WB1 (contiguous)
__device__ __forceinline__ void stage_w2(u32 sm0, const float* __restrict__ gW2, int tid) {
    const u32 dW = sm0 + WB0 * 4u;
#pragma unroll
    for (int i = 0; i < 16; ++i) {
        const int idx = i * 256 + tid;
        const int k = idx >> 5, j = (idx & 31) * 4;
        cp16(dW + (u32)(k * 128 + j) * 4u, gW2 + k * 128 + j);
    }
}

// full 2-layer MLP for this block's 128-token tile; result (layer2 + bias2) in accOut
__device__ __forceinline__ void mlp_pass(const float* __restrict__ gW1, const float* __restrict__ gB1,
                                         const float* __restrict__ gW2, const float* __restrict__ gB2,
                                         const float* __restrict__ gXtile,
                                         float* smf, u32 sm0, int tid, int t0, int c0,
                                         u64 accOut[4][8]) {
    u64 acc1[4][8];
    {
        const u64* b1p = (const u64*)(gB1 + c0);
        u64 b0 = b1p[0], b1 = b1p[1], b2 = b1p[2], b3 = b1p[3];
#pragma unroll
        for (int t = 0; t < 8; ++t) { acc1[0][t] = b0; acc1[1][t] = b1; acc1[2][t] = b2; acc1[3][t] = b3; }
    }
    stage_chunk(sm0, 0, gXtile, gW1, 0, tid);
    CP_COMMIT();
#pragma unroll 1
    for (int kc = 0; kc < 16; ++kc) {
        if (kc < 15) {
            stage_chunk(sm0, (kc + 1) & 1, gXtile, gW1, kc + 1, tid);
            CP_COMMIT();
            cp_wait<1>();
        } else {
            cp_wait<0>();
        }
        __syncthreads();
        const float* Xs = smf + ((kc & 1) ? XB1 : XB0);
        const float* Ws = smf + ((kc & 1) ? WB1 : WB0);
        mma_chunk64(Xs, Ws, t0, c0, acc1);
        __syncthreads();
    }
    // GELU -> hs [hidden ch][token]
    float* hsm = smf + HSOFF;
#pragma unroll
    for (int cp = 0; cp < 4; ++cp) {
        float vA[8], vB[8];
#pragma unroll
        for (int j = 0; j < 8; ++j) {
            float lo, hi; upk2(acc1[cp][j], lo, hi);
            vA[j] = gelu_exact(lo); vB[j] = gelu_exact(hi);
        }
        float* rA = hsm + (c0 + 2 * cp) * 132 + t0;
        float* rB = rA + 132;
        *(float4*)rA       = make_float4(vA[0], vA[1], vA[2], vA[3]);
        *(float4*)(rA + 4) = make_float4(vA[4], vA[5], vA[6], vA[7]);
        *(float4*)rB       = make_float4(vB[0], vB[1], vB[2], vB[3]);
        *(float4*)(rB + 4) = make_float4(vB[4], vB[5], vB[6], vB[7]);
    }
    __syncthreads();
    // layer2
    stage_w2(sm0, gW2, tid);
    CP_COMMIT();
    cp_wait<0>();
    __syncthreads();
    {
        const u64* b2p = (const u64*)(gB2 + c0);
        u64 b0 = b2p[0], b1 = b2p[1], b2 = b2p[2], b3 = b2p[3];
#pragma unroll
        for (int t = 0; t < 8; ++t) { accOut[0][t] = b0; accOut[1][t] = b1; accOut[2][t] = b2; accOut[3][t] = b3; }
    }
    mma_chunk64(hsm,            smf + WB0,            t0, c0, accOut);
    mma_chunk64(hsm + 64 * 132, smf + WB0 + 64 * 128, t0, c0, accOut);
    __syncthreads();   // hs free for reuse by next MLP
}

// ---------------------------------------------------------------
// Kernel 1: both MLPs + pointwise. 256 blocks x 256 threads.
// ---------------------------------------------------------------
__global__ void __launch_bounds__(256, 1)
k_fused(const float* __restrict__ theta,
        const float* __restrict__ logQ, const float* __restrict__ logRa,
        const float* __restrict__ rw1, const float* __restrict__ rb1,
        const float* __restrict__ rw2, const float* __restrict__ rb2,
        const float* __restrict__ mw1, const float* __restrict__ mb1,
        const float* __restrict__ mw2, const float* __restrict__ mb2,
        float* __restrict__ out) {
    extern __shared__ float smf[];
    const u32 sm0 = (u32)__cvta_generic_to_shared(smf);
    const int tid = threadIdx.x;
    const int tile = blockIdx.x;
    const int n0 = tile * NTOK;
    const int t0 = (tid & 15) * 8;
    const int c0 = (tid >> 4) * 8;
    const float* gXtile = g_xT + (size_t)tile * 131072;

    // ---- MLP R ----
    u64 accR[4][8];
    mlp_pass(rw1, rb1, rw2, rb2, gXtile, smf, sm0, tid, t0, c0, accR);
    // R = exp(clip(.,-5,5)) -> write out segment 3 (also re-read at pointwise)
#pragma unroll
    for (int j = 0; j < 8; ++j) {
        float r8[8];
#pragma unroll
        for (int cp = 0; cp < 4; ++cp) {
            float lo, hi; upk2(accR[cp][j], lo, hi);
            r8[2 * cp]     = expf(fminf(fmaxf(lo, -5.0f), 5.0f));
            r8[2 * cp + 1] = expf(fminf(fmaxf(hi, -5.0f), 5.0f));
        }
        float* p = out + 3 * SEG + (n0 + t0 + j) * NCH + c0;
        *(float4*)p       = make_float4(r8[0], r8[1], r8[2], r8[3]);
        *(float4*)(p + 4) = make_float4(r8[4], r8[5], r8[6], r8[7]);
    }

    // ---- MLP M ----
    u64 accM[4][8];
    mlp_pass(mw1, mb1, mw2, mb2, gXtile, smf, sm0, tid, t0, c0, accM);

    // ---- Pi per channel ----
    float Pi8[8];
#pragma unroll
    for (int i = 0; i < 8; ++i) {
        const int c = c0 + i;
        const float q = expf(logQ[c]);
        const float ra = expf(logRa[c]);
        Pi8[i] = 0.5f * (sqrtf(q * q + 4.0f * q * ra) - q);
    }

    // ---- pointwise + outputs ----
    const float PI_F = 3.14159265358979323f;
    const float TWO_PI = 6.28318530717958648f;
    const float INV_2PI = 0.15915494309189535f;
#pragma unroll
    for (int j = 0; j < 8; ++j) {
        const int n = n0 + t0 + j;
        const int base = n * NCH + c0;
        float m8[8];
#pragma unroll
        for (int cp = 0; cp < 4; ++cp) upk2(accM[cp][j], m8[2 * cp], m8[2 * cp + 1]);
        const float4 ra4 = *(const float4*)(out + 3 * SEG + base);
        const float4 rb4 = *(const float4*)(out + 3 * SEG + base + 4);
        const float r8[8] = {ra4.x, ra4.y, ra4.z, ra4.w, rb4.x, rb4.y, rb4.z, rb4.w};
        const float4 ta4 = *(const float4*)(theta + base);
        const float4 tb4 = *(const float4*)(theta + base + 4);
        const float th8[8] = {ta4.x, ta4.y, ta4.z, ta4.w, tb4.x, tb4.y, tb4.z, tb4.w};
        float k8[8], av8[8], uv8[8];
#pragma unroll
        for (int i = 0; i < 8; ++i) {
            const float z = PI_F * tanhf(m8[i]);
            const float diff = z - th8[i];
            const float nu = diff - TWO_PI * rintf(diff * INV_2PI);
            const float Kv = Pi8[i] / fmaxf(Pi8[i] + r8[i], 1e-8f);
            k8[i] = Kv;
            av8[i] = 1.0f - Kv;
            uv8[i] = Kv * nu;
        }
        float* pp = out + SEG + base;
        *(float4*)pp       = make_float4(Pi8[0], Pi8[1], Pi8[2], Pi8[3]);
        *(float4*)(pp + 4) = make_float4(Pi8[4], Pi8[5], Pi8[6], Pi8[7]);
        float* pk = out + 2 * SEG + base;
        *(float4*)pk       = make_float4(k8[0], k8[1], k8[2], k8[3]);
        *(float4*)(pk + 4) = make_float4(k8[4], k8[5], k8[6], k8[7]);
        float* pa = (float*)g_au + 2 * base;
        *(float4*)pa        = make_float4(av8[0], uv8[0], av8[1], uv8[1]);
        *(float4*)(pa + 4)  = make_float4(av8[2], uv8[2], av8[3], uv8[3]);
        *(float4*)(pa + 8)  = make_float4(av8[4], uv8[4], av8[5], uv8[5]);
        *(float4*)(pa + 12) = make_float4(av8[6], uv8[6], av8[7], uv8[7]);
    }
}

// ---------------------------------------------------------------
// Scan kernels: chunked affine scan over seq dim (chunk = 128 steps)
// ---------------------------------------------------------------
__global__ void k_scanA() {
    const int c = blockIdx.x, b = blockIdx.y, t = threadIdx.x;
    int base = (b * SEQ + c * 128) * NCH + t;
    float A = 1.0f, U = 0.0f;
#pragma unroll 4
    for (int s = 0; s < 128; ++s) {
        float2 au = g_au[base + s * NCH];
        A *= au.x;
        U = fmaf(au.x, U, au.y);
    }
    g_agg[(b * 32 + c) * NCH + t] = make_float2(A, U);
}

__global__ void k_scanB() {
    const int b = blockIdx.x, t = threadIdx.x;
    float U = 0.0f;
#pragma unroll
    for (int c = 0; c < 32; ++c) {
        float2 g = g_agg[(b * 32 + c) * NCH + t];
        g_carry[(b * 32 + c) * NCH + t] = U;
        U = fmaf(g.x, U, g.y);
    }
}

__global__ void k_scanC(const float* __restrict__ theta, float* __restrict__ out) {
    const int c = blockIdx.x, b = blockIdx.y, t = threadIdx.x;
    int base = (b * SEQ + c * 128) * NCH + t;
    float d = g_carry[(b * 32 + c) * NCH + t];
#pragma unroll 4
    for (int s = 0; s < 128; ++s) {
        const int idx = base + s * NCH;
        float2 au = g_au[idx];
        d = fmaf(au.x, d, au.y);
        out[idx] = theta[idx] + d;
    }
}

// ---------------------------------------------------------------
extern "C" void kernel_launch(void* const* d_in, const int* in_sizes, int n_in,
                              void* d_out, int out_size) {
    const float* theta = (const float*)d_in[0];
    const float* ce    = (const float*)d_in[1];
    const float* logQ  = (const float*)d_in[2];
    const float* logRa = (const float*)d_in[3];
    const float* rw1   = (const float*)d_in[4];
    const float* rb1   = (const float*)d_in[5];
    const float* rw2   = (const float*)d_in[6];
    const float* rb2   = (const float*)d_in[7];
    const float* mw1   = (const float*)d_in[8];
    const float* mb1   = (const float*)d_in[9];
    const float* mw2   = (const float*)d_in[10];
    const float* mb2   = (const float*)d_in[11];
    float* out = (float*)d_out;

    k_transpose<<<dim3(32, 1024), dim3(32, 8)>>>(ce);

    const int smem = SMEMF * (int)sizeof(float);  // 200704 bytes
    cudaFuncSetAttribute(k_fused, cudaFuncAttributeMaxDynamicSharedMemorySize, smem);
    k_fused<<<256, 256, smem>>>(theta, logQ, logRa,
                                rw1, rb1, rw2, rb2,
                                mw1, mb1, mw2, mb2, out);

    k_scanA<<<dim3(32, BATCH), 128>>>();
    k_scanB<<<BATCH, 128>>>();
    k_scanC<<<dim3(32, BATCH), 128>>>(theta, out);
}